// round 10
// baseline (speedup 1.0000x reference)
#include <cuda_runtime.h>
#include <cuda_bf16.h>

// SpanIndexEncoder: out[t] = sum over nodes n (n<num_nodes, s_n<=t<=e_n) of emb[n]
// Sparse boundary events in per-QUARTER (4-token) lists; 3-kernel pipeline:
//   A: classify events into per-quarter lists (scalar atomics)
//   BC: FUSED quarter sums + block-parallel exclusive scan (64 col-blocks x 1024 thr)
//   D: apply, one quarter per block (2048 blocks x 256 thr): single accumulator per
//      thread, batched predicated adds; self-resets counters (no memset nodes).

#define MAX_TOKENS 8192
#define MAX_NODES  8192
#define FEAT       256
#define F4         (FEAT / 4)        // 64 float4 columns
#define NQ         (MAX_TOKENS / 4)  // 2048 quarters
#define CAP_Q      16384             // absolute worst case events in one quarter

// event word: bits[0:13)=node, bits[13:15)=token-within-quarter, bit15=sign(1=minus)
__device__ unsigned g_qev[(size_t)NQ * CAP_Q];
__device__ int      g_qcnt[NQ];          // self-resetting
__device__ float    g_q[NQ * FEAT];      // exclusive quarter prefixes

__device__ __forceinline__ void f4acc(float4& a, const float4 b) {
    a.x += b.x; a.y += b.y; a.z += b.z; a.w += b.w;
}
__device__ __forceinline__ float4 sgn_row(const float4* emb4, unsigned w, int j) {
    const float sg = (w & (1u << 15)) ? -1.f : 1.f;
    const float4 v = emb4[(size_t)(w & 8191u) * F4 + j];
    return make_float4(sg * v.x, sg * v.y, sg * v.z, sg * v.w);
}

// ---- A: classify span boundaries into per-quarter lists ----
__global__ void __launch_bounds__(256) classify_kernel(
    const int* __restrict__ starts,
    const int* __restrict__ ends,
    const int* __restrict__ num_nodes_p)
{
    const int n = blockIdx.x * 256 + threadIdx.x;
    if (n >= num_nodes_p[0]) return;
    const int s = starts[n];
    const int e = ends[n];
    if (s > e) return;

    int q = s >> 2;
    int p = atomicAdd(&g_qcnt[q], 1);
    g_qev[(size_t)q * CAP_Q + p] = (unsigned)n | ((unsigned)(s & 3) << 13);

    const int e1 = e + 1;
    if (e1 < MAX_TOKENS) {
        q = e1 >> 2;
        p = atomicAdd(&g_qcnt[q], 1);
        g_qev[(size_t)q * CAP_Q + p] = (unsigned)n | ((unsigned)(e1 & 3) << 13) | (1u << 15);
    }
}

// ---- BC: fused quarter sums + exclusive scan. Grid: 64 blocks (one float4 col), 1024 thr.
// Thread owns quarters 2*tid and 2*tid+1; gathers their signed rows (independent -> MLP),
// then warp shfl scan + cross-warp scan in shared produce exclusive prefixes.
__global__ void __launch_bounds__(1024) sumscan_kernel(const float* __restrict__ emb)
{
    const int j    = blockIdx.x;       // float4 column
    const int tid  = threadIdx.x;
    const int lane = tid & 31;
    const int wid  = tid >> 5;
    const int q0   = tid * 2;
    const int q1   = q0 + 1;

    const float4* emb4 = reinterpret_cast<const float4*>(emb);
    const unsigned* e0 = g_qev + (size_t)q0 * CAP_Q;
    const unsigned* e1 = g_qev + (size_t)q1 * CAP_Q;
    const int c0 = g_qcnt[q0];
    const int c1 = g_qcnt[q1];

    float4 s0 = make_float4(0.f, 0.f, 0.f, 0.f);
    float4 s1 = make_float4(0.f, 0.f, 0.f, 0.f);
    const int m = c0 > c1 ? c0 : c1;
    for (int i = 0; i < m; ++i) {      // interleave both quarters -> 2-way MLP per iter
        if (i < c0) f4acc(s0, sgn_row(emb4, e0[i], j));
        if (i < c1) f4acc(s1, sgn_row(emb4, e1[i], j));
    }

    float4 tot = s0; f4acc(tot, s1);

    // warp inclusive scan of tot
    float4 incl = tot;
#pragma unroll
    for (int d = 1; d < 32; d <<= 1) {
        const float tx = __shfl_up_sync(0xffffffffu, incl.x, d);
        const float ty = __shfl_up_sync(0xffffffffu, incl.y, d);
        const float tz = __shfl_up_sync(0xffffffffu, incl.z, d);
        const float tw = __shfl_up_sync(0xffffffffu, incl.w, d);
        if (lane >= d) { incl.x += tx; incl.y += ty; incl.z += tz; incl.w += tw; }
    }

    __shared__ float4 wsum[32];
    if (lane == 31) wsum[wid] = incl;
    __syncthreads();
    if (wid == 0) {
        float4 v = wsum[lane];
        float4 wi = v;
#pragma unroll
        for (int d = 1; d < 32; d <<= 1) {
            const float tx = __shfl_up_sync(0xffffffffu, wi.x, d);
            const float ty = __shfl_up_sync(0xffffffffu, wi.y, d);
            const float tz = __shfl_up_sync(0xffffffffu, wi.z, d);
            const float tw = __shfl_up_sync(0xffffffffu, wi.w, d);
            if (lane >= d) { wi.x += tx; wi.y += ty; wi.z += tz; wi.w += tw; }
        }
        wsum[lane] = make_float4(wi.x - v.x, wi.y - v.y, wi.z - v.z, wi.w - v.w);
    }
    __syncthreads();

    const float4 base = wsum[wid];
    // exclusive prefix for q0 = warp base + (inclusive-within-warp minus own total)
    float4 ex = make_float4(base.x + incl.x - tot.x, base.y + incl.y - tot.y,
                            base.z + incl.z - tot.z, base.w + incl.w - tot.w);

    *reinterpret_cast<float4*>(&g_q[(size_t)q0 * FEAT + (j << 2)]) = ex;
    f4acc(ex, s0);
    *reinterpret_cast<float4*>(&g_q[(size_t)q1 * FEAT + (j << 2)]) = ex;
}

// ---- D: apply. 2048 blocks (one quarter) x 256 thr: thread (t=tid>>6, j=tid&63) ----
__global__ void __launch_bounds__(256) apply_kernel(
    const float* __restrict__ emb,
    float*       __restrict__ out)
{
    const int q   = blockIdx.x;
    const int tid = threadIdx.x;
    const int j   = tid & 63;
    const int t   = tid >> 6;          // token-within-quarter this thread owns

    const int cnt = g_qcnt[q];
    const unsigned* evq = g_qev + (size_t)q * CAP_Q;
    const float4* emb4 = reinterpret_cast<const float4*>(emb);

    float4 r = *reinterpret_cast<const float4*>(&g_q[(size_t)q * FEAT + (j << 2)]);

    int i = 0;
    for (; i + 4 <= cnt; i += 4) {     // 4-wide batch: all word + row loads independent
        const unsigned w0 = evq[i], w1 = evq[i + 1], w2 = evq[i + 2], w3 = evq[i + 3];
        const float4 v0 = sgn_row(emb4, w0, j);
        const float4 v1 = sgn_row(emb4, w1, j);
        const float4 v2 = sgn_row(emb4, w2, j);
        const float4 v3 = sgn_row(emb4, w3, j);
        const float p0 = (int)((w0 >> 13) & 3) <= t ? 1.f : 0.f;
        const float p1 = (int)((w1 >> 13) & 3) <= t ? 1.f : 0.f;
        const float p2 = (int)((w2 >> 13) & 3) <= t ? 1.f : 0.f;
        const float p3 = (int)((w3 >> 13) & 3) <= t ? 1.f : 0.f;
        r.x += p0 * v0.x + p1 * v1.x + p2 * v2.x + p3 * v3.x;
        r.y += p0 * v0.y + p1 * v1.y + p2 * v2.y + p3 * v3.y;
        r.z += p0 * v0.z + p1 * v1.z + p2 * v2.z + p3 * v3.z;
        r.w += p0 * v0.w + p1 * v1.w + p2 * v2.w + p3 * v3.w;
    }
    for (; i < cnt; ++i) {
        const unsigned w = evq[i];
        const float4 v = sgn_row(emb4, w, j);
        const float p = (int)((w >> 13) & 3) <= t ? 1.f : 0.f;
        r.x += p * v.x; r.y += p * v.y; r.z += p * v.z; r.w += p * v.w;
    }

    *reinterpret_cast<float4*>(out + (size_t)(q * 4 + t) * FEAT + (j << 2)) = r;

    // self-reset for next graph replay (all threads consumed cnt above)
    __syncthreads();
    if (tid == 0) g_qcnt[q] = 0;
}

extern "C" void kernel_launch(void* const* d_in, const int* in_sizes, int n_in,
                              void* d_out, int out_size)
{
    const float* emb    = (const float*)d_in[0];
    const int*   starts = (const int*)d_in[1];
    const int*   ends   = (const int*)d_in[2];
    const int*   nnp    = (const int*)d_in[3];
    float*       out    = (float*)d_out;

    classify_kernel<<<MAX_NODES / 256, 256>>>(starts, ends, nnp);
    sumscan_kernel<<<F4, 1024>>>(emb);
    apply_kernel<<<NQ, 256>>>(emb, out);
}